// round 6
// baseline (speedup 1.0000x reference)
#include <cuda_runtime.h>
#include <cuda_bf16.h>
#include <cstdint>

#define IN_DIM 10
#define H      100
#define OUT_D  10
#define Ln     5
#define Bn     64
#define Tn     2048
#define M_ROWS (Bn * Tn)          // 131072
#define CCH    64                 // gemm chunk (timesteps)
#define NCHUNK (Tn / CCH)         // 32
#define NGEMM  124                // gemm CTAs (31 per layer 1..4)
#define NREC   (Ln * Bn)          // 320
#define GRID_F (NGEMM + NREC)     // 444 = 148*3

// Activations / transformed inputs: [l][b][t][j]
__device__ float g_xp[(size_t)Ln * Bn * Tn * H];   // xp_l (input transform incl. biases)
__device__ float g_h [(size_t)Ln * Bn * Tn * H];   // h_l outputs
// Flags: [0,320) rec progress (steps published), [320,576) xp rows ready
__device__ int   g_flags[NREC + 4 * Bn];

// ---------------- f32x2 helpers ----------------
__device__ __forceinline__ unsigned long long fma2(unsigned long long a,
                                                   unsigned long long b,
                                                   unsigned long long c) {
    unsigned long long d;
    asm("fma.rn.f32x2 %0, %1, %2, %3;" : "=l"(d) : "l"(a), "l"(b), "l"(c));
    return d;
}
__device__ __forceinline__ unsigned long long add2(unsigned long long a,
                                                   unsigned long long b) {
    unsigned long long d;
    asm("add.rn.f32x2 %0, %1, %2;" : "=l"(d) : "l"(a), "l"(b));
    return d;
}
__device__ __forceinline__ unsigned long long pack2(float lo, float hi) {
    unsigned long long d;
    asm("mov.b64 %0, {%1, %2};" : "=l"(d) : "f"(lo), "f"(hi));
    return d;
}
__device__ __forceinline__ void unpack2(unsigned long long a, float& lo, float& hi) {
    asm("mov.b64 {%0, %1}, %2;" : "=f"(lo), "=f"(hi) : "l"(a));
}
__device__ __forceinline__ int acq_load(const int* p) {
    int v;
    asm volatile("ld.global.acquire.gpu.b32 %0, [%1];" : "=r"(v) : "l"(p) : "memory");
    return v;
}
// L2-coherent load (bypass L1) for data written concurrently by other CTAs.
__device__ __forceinline__ float ldcg(const float* p) {
    float v;
    asm volatile("ld.global.cg.f32 %0, [%1];" : "=f"(v) : "l"(p) : "memory");
    return v;
}
__device__ __forceinline__ float4 ldcg4(const float4* p) {
    float4 v;
    asm volatile("ld.global.cg.v4.f32 {%0,%1,%2,%3}, [%4];"
                 : "=f"(v.x), "=f"(v.y), "=f"(v.z), "=f"(v.w) : "l"(p) : "memory");
    return v;
}

// ---------------- flag reset (graph-replay determinism) ----------------
__global__ void zflags_kernel() {
    if (threadIdx.x < NREC + 4 * Bn) g_flags[threadIdx.x] = 0;
}

// ---------------- layer-0 input transform: xp0 = x @ Wih0^T + b ----------------
__global__ void __launch_bounds__(128) gemm0_kernel(
    const float* __restrict__ X, const float* __restrict__ W,
    const float* __restrict__ b1, const float* __restrict__ b2,
    float* __restrict__ Y)
{
    __shared__ __align__(16) float Ws[IN_DIM * H];
    __shared__ __align__(16) float bs[H];
    const int tid = threadIdx.x;
    for (int idx = tid; idx < IN_DIM * H; idx += 128) {
        int j = idx / IN_DIM, k = idx - j * IN_DIM;
        Ws[k * H + j] = W[idx];
    }
    if (tid < H) bs[tid] = b1[tid] + b2[tid];
    __syncthreads();

    const int row = blockIdx.x * 128 + tid;
    if (row >= M_ROWS) return;

    unsigned long long acc[50];
    const unsigned long long* bp = (const unsigned long long*)bs;
#pragma unroll
    for (int i = 0; i < 50; i++) acc[i] = bp[i];
    const float* xr = X + (size_t)row * IN_DIM;
#pragma unroll
    for (int k = 0; k < IN_DIM; k++) {
        float xk = xr[k];
        unsigned long long xkk = pack2(xk, xk);
        const ulonglong2* wr = (const ulonglong2*)(Ws + k * H);
#pragma unroll
        for (int i = 0; i < 25; i++) {
            ulonglong2 wv = wr[i];
            acc[2 * i]     = fma2(xkk, wv.x, acc[2 * i]);
            acc[2 * i + 1] = fma2(xkk, wv.y, acc[2 * i + 1]);
        }
    }
    unsigned long long* yr = (unsigned long long*)(Y + (size_t)row * H);
#pragma unroll
    for (int i = 0; i < 50; i++) yr[i] = acc[i];
}

// ---------------- fused wavefront kernel ----------------
// blockIdx [0, NGEMM): gemm CTA for layers 1..4 (xp_l from h_{l-1})
// blockIdx [NGEMM, NGEMM+NREC): recurrent CTA (l = r/64, b = r%64)
#define SM_WO 0
#define SM_HB 41600
#define SM_BS 67456
#define SM_SZ 68096

__global__ void __launch_bounds__(128, 3) fused_kernel(
    const float* __restrict__ Wih,   // [4][H][H]  (layers 1..4)
    const float* __restrict__ Whh,   // [5][H][H]
    const float* __restrict__ bih,   // [5][H]
    const float* __restrict__ bhh,   // [5][H]
    const float* __restrict__ h0,    // [5][Bn][H]
    float* __restrict__ hf)          // [5][Bn][H] final hidden out
{
    extern __shared__ __align__(16) unsigned char smraw[];
    const int tid = threadIdx.x;
    const int bid = blockIdx.x;

    if (bid < NGEMM) {
        // ======================= GEMM CTA =======================
        const int l = 1 + bid / 31;          // 1..4
        const int r = bid % 31;              // batch group
        unsigned long long* Wo = (unsigned long long*)(smraw + SM_WO);
        float*              hb = (float*)(smraw + SM_HB);
        unsigned long long* bsm = (unsigned long long*)(smraw + SM_BS);

        const float* W = Wih + (size_t)(l - 1) * H * H;
        for (int idx = tid; idx < H * 50; idx += 128) {
            int k = idx % H, m = idx / H;
            int half = m / 25, i = m - half * 25;
            Wo[k * 52 + half * 26 + i] = pack2(W[(2 * m) * H + k], W[(2 * m + 1) * H + k]);
        }
        for (int m = tid; m < 50; m += 128) {
            float blo = bih[l * H + 2 * m] + bhh[l * H + 2 * m];
            float bhi = bih[l * H + 2 * m + 1] + bhh[l * H + 2 * m + 1];
            bsm[m] = pack2(blo, bhi);
        }
        __syncthreads();

        const int row  = tid & 63;           // 0..63 within chunk
        const int half = tid >> 6;           // 0..1 (output half)
        const int nb = (r < 2) ? 3 : 2;

        for (int c = 0; c < NCHUNK; c++) {
            for (int ib = 0; ib < nb; ib++) {
                const int b = r + 31 * ib;
                const int need = (c + 1) * CCH;
                const int* rf = &g_flags[(l - 1) * Bn + b];
                while (acq_load(rf) < need) { }

                // Stage h_{l-1}[b][c*CCH .. +CCH) into hb via .cg (L2-coherent)
                const float* src = g_h + (((size_t)(l - 1) * Bn + b) * Tn + (size_t)c * CCH) * H;
                for (int idx = tid; idx < CCH * H; idx += 128) {
                    int rr = idx / H, k = idx - rr * H;
                    hb[rr * 101 + k] = ldcg(src + idx);
                }
                __syncthreads();

                unsigned long long acc[25];
#pragma unroll
                for (int i = 0; i < 25; i++) acc[i] = bsm[half * 25 + i];
                const float* hrow = hb + row * 101;
#pragma unroll 2
                for (int k = 0; k < H; k++) {
                    float xk = hrow[k];
                    unsigned long long xkk = pack2(xk, xk);
                    const unsigned long long* Wk = Wo + k * 52 + half * 26;
#pragma unroll
                    for (int i = 0; i < 25; i++) acc[i] = fma2(xkk, Wk[i], acc[i]);
                }
                unsigned long long* dst = (unsigned long long*)
                    (g_xp + (((size_t)l * Bn + b) * Tn + (size_t)c * CCH + row) * H + half * 50);
#pragma unroll
                for (int i = 0; i < 25; i++) dst[i] = acc[i];
                __syncthreads();
                if (tid == 0) {
                    __threadfence();
                    *(volatile int*)&g_flags[NREC + (l - 1) * Bn + b] = need;
                }
            }
        }
        return;
    }

    // ======================= RECURRENT CTA =======================
    const int rb = bid - NGEMM;
    const int l = rb / Bn;
    const int b = rb % Bn;
    const int j = tid;

    float* hs = (float*)smraw;               // [2][104]
    float* hs0 = hs;
    float* hs1 = hs + 104;

    unsigned long long w[50];
    if (j < H) {
        const unsigned long long* wr = (const unsigned long long*)(Whh + ((size_t)l * H + j) * H);
#pragma unroll
        for (int i = 0; i < 50; i++) w[i] = wr[i];
        hs0[j] = h0[((size_t)l * Bn + b) * H + j];
    }
    __syncthreads();

    const float* xp = g_xp + ((size_t)l * Bn + b) * Tn * H;
    float* hout = g_h + ((size_t)l * Bn + b) * Tn * H;
    const int* srcflag = (l > 0) ? &g_flags[NREC + (l - 1) * Bn + b] : nullptr;
    volatile int* pubflag = (l < 4) ? (volatile int*)&g_flags[l * Bn + b] : nullptr;

    int seen = 0;
    if (l > 0) { while (seen < 1) seen = acq_load(srcflag); }
    // .cg for xp: layers 1..4 are produced concurrently by gemm CTAs (must
    // bypass L1); harmless extra latency for layer 0 (off dependency chain).
    float xv = (j < H) ? ldcg(xp + j) : 0.f;

#pragma unroll 1
    for (int t = 0; t < Tn; t++) {
        float xnext = 0.f;
        if (t + 1 < Tn) {
            if (l > 0) { while (seen < t + 2) seen = acq_load(srcflag); }
            if (j < H) xnext = ldcg(xp + (size_t)(t + 1) * H + j);
        }
        const int p = t & 1;
        if (j < H) {
            const ulonglong2* hp = (const ulonglong2*)(p ? hs1 : hs0);
            unsigned long long a0 = 0ull, a1 = 0ull, a2 = 0ull, a3 = 0ull;
#pragma unroll
            for (int i = 0; i < 25; i++) {
                ulonglong2 hv = hp[i];
                if (i & 1) {
                    a2 = fma2(w[2 * i],     hv.x, a2);
                    a3 = fma2(w[2 * i + 1], hv.y, a3);
                } else {
                    a0 = fma2(w[2 * i],     hv.x, a0);
                    a1 = fma2(w[2 * i + 1], hv.y, a1);
                }
            }
            unsigned long long s2 = add2(add2(a0, a2), add2(a1, a3));
            float slo, shi;
            unpack2(s2, slo, shi);
            float s = slo + shi + xv;
            float e  = __expf(2.0f * s);
            float th = 1.0f - __fdividef(2.0f, e + 1.0f);
            (p ? hs0 : hs1)[j] = th;
            hout[(size_t)t * H + j] = th;
        }
        __syncthreads();
        if (pubflag != nullptr && tid == 0) {
            __threadfence();
            *pubflag = t + 1;
        }
        xv = xnext;
    }

    if (j < H) hf[((size_t)l * Bn + b) * H + j] = hs0[j];  // T even -> final in hs0
}

// ---------------- output projection ----------------
__global__ void __launch_bounds__(128) proj_kernel(
    const float* __restrict__ X, const float* __restrict__ Wout,
    const float* __restrict__ bout, float* __restrict__ Y)
{
    __shared__ __align__(16) float Ws[H * 12];
    __shared__ __align__(16) float bs[12];
    const int tid = threadIdx.x;
    for (int i = tid; i < H * 12; i += 128) Ws[i] = 0.f;
    if (tid < 12) bs[tid] = (tid < OUT_D) ? bout[tid] : 0.f;
    __syncthreads();
    for (int idx = tid; idx < OUT_D * H; idx += 128) {
        int j = idx / H, k = idx - j * H;
        Ws[k * 12 + j] = Wout[idx];
    }
    __syncthreads();

    const int row = blockIdx.x * 128 + tid;
    if (row >= M_ROWS) return;

    unsigned long long acc[5];
    const unsigned long long* bp = (const unsigned long long*)bs;
#pragma unroll
    for (int i = 0; i < 5; i++) acc[i] = bp[i];
    const float4* xr = (const float4*)(X + (size_t)row * H);
#pragma unroll 1
    for (int k4 = 0; k4 < 25; k4++) {
        float4 xv = xr[k4];
        float xs[4] = {xv.x, xv.y, xv.z, xv.w};
#pragma unroll
        for (int u = 0; u < 4; u++) {
            int k = k4 * 4 + u;
            unsigned long long xkk = pack2(xs[u], xs[u]);
            const unsigned long long* wr = (const unsigned long long*)(Ws + k * 12);
#pragma unroll
            for (int i = 0; i < 5; i++) acc[i] = fma2(xkk, wr[i], acc[i]);
        }
    }
    unsigned long long* yr = (unsigned long long*)(Y + (size_t)row * OUT_D);
#pragma unroll
    for (int i = 0; i < 5; i++) yr[i] = acc[i];
}

// ---------------- launcher ----------------
extern "C" void kernel_launch(void* const* d_in, const int* in_sizes, int n_in,
                              void* d_out, int out_size)
{
    const float* x    = (const float*)d_in[0];
    const float* h0   = (const float*)d_in[1];   // [L,B,H]
    const float* Wih0 = (const float*)d_in[2];   // [H,IN]
    const float* Wih  = (const float*)d_in[3];   // [L-1,H,H]
    const float* Whh  = (const float*)d_in[4];   // [L,H,H]
    const float* bih  = (const float*)d_in[5];   // [L,H]
    const float* bhh  = (const float*)d_in[6];   // [L,H]
    const float* Wout = (const float*)d_in[7];   // [OUT,H]
    const float* bout = (const float*)d_in[8];   // [OUT]

    float* y  = (float*)d_out;                        // [B,T,OUT]
    float* hf = y + (size_t)Bn * Tn * OUT_D;          // [L,B,H]

    float *xp0, *hbuf;
    cudaGetSymbolAddress((void**)&xp0,  g_xp);
    cudaGetSymbolAddress((void**)&hbuf, g_h);

    cudaFuncSetAttribute(fused_kernel, cudaFuncAttributeMaxDynamicSharedMemorySize, SM_SZ);

    zflags_kernel<<<1, 1024>>>();
    gemm0_kernel<<<(M_ROWS + 127) / 128, 128>>>(x, Wih0, bih, bhh, xp0);
    fused_kernel<<<GRID_F, 128, SM_SZ>>>(Wih, Whh, bih, bhh, h0, hf);
    proj_kernel<<<(M_ROWS + 127) / 128, 128>>>(hbuf + (size_t)4 * Bn * Tn * H, Wout, bout, y);
}

// round 7
// speedup vs baseline: 4.2418x; 4.2418x over previous
#include <cuda_runtime.h>
#include <cuda_bf16.h>
#include <cstdint>

#define IN_DIM 10
#define H      100
#define OUT_D  10
#define Ln     5
#define Bn     64
#define Tn     2048
#define M_ROWS (Bn * Tn)          // 131072
#define CCH    64                 // chunk (timesteps)
#define NCHUNK (Tn / CCH)         // 32
#define NGEMM  124                // gemm CTAs (31 per layer 1..4)
#define NREC   (Ln * Bn)          // 320
#define GRID_F (NGEMM + NREC)     // 444 = 148*3
#define NFLAGS (NREC + Ln * Bn)   // 640: [0,320) rec h progress, [320,640) xp ready

// Activations / transformed inputs: [l][b][t][j]
__device__ float g_xp[(size_t)Ln * Bn * Tn * H];
__device__ float g_h [(size_t)Ln * Bn * Tn * H];
__device__ int   g_flags[NFLAGS];

// ---------------- f32x2 helpers ----------------
__device__ __forceinline__ unsigned long long fma2(unsigned long long a,
                                                   unsigned long long b,
                                                   unsigned long long c) {
    unsigned long long d;
    asm("fma.rn.f32x2 %0, %1, %2, %3;" : "=l"(d) : "l"(a), "l"(b), "l"(c));
    return d;
}
__device__ __forceinline__ unsigned long long add2(unsigned long long a,
                                                   unsigned long long b) {
    unsigned long long d;
    asm("add.rn.f32x2 %0, %1, %2;" : "=l"(d) : "l"(a), "l"(b));
    return d;
}
__device__ __forceinline__ unsigned long long pack2(float lo, float hi) {
    unsigned long long d;
    asm("mov.b64 %0, {%1, %2};" : "=l"(d) : "f"(lo), "f"(hi));
    return d;
}
__device__ __forceinline__ void unpack2(unsigned long long a, float& lo, float& hi) {
    asm("mov.b64 {%0, %1}, %2;" : "=f"(lo), "=f"(hi) : "l"(a));
}
__device__ __forceinline__ int acq_load(const int* p) {
    int v;
    asm volatile("ld.global.acquire.gpu.b32 %0, [%1];" : "=r"(v) : "l"(p) : "memory");
    return v;
}
// L2-coherent load (bypass L1): required for data written concurrently by
// other CTAs in the same launch.
__device__ __forceinline__ float ldcg(const float* p) {
    float v;
    asm volatile("ld.global.cg.f32 %0, [%1];" : "=f"(v) : "l"(p) : "memory");
    return v;
}

__global__ void zflags_kernel() {
    if (threadIdx.x < NFLAGS) g_flags[threadIdx.x] = 0;
}

// ---------------- fused wavefront kernel ----------------
// bid in [0, NGEMM): gemm CTA. Phase 1 (bid<64): compute xp0 for batch=bid.
//   Phase 2: input-transform for layer l = 1 + bid/31 (2-3 batches).
// bid in [NGEMM, NGEMM+NREC): recurrent CTA (l = r/64, b = r%64).
#define SM_WO 0        // u64[100][2][26]  staged Wih (pair-major, padded)
#define SM_HB 41600    // float[64][101]   staged h chunk
#define SM_BS 67456    // u64[50]          bias pairs
#define SM_SZ 68096

__global__ void __launch_bounds__(128, 3) fused_kernel(
    const float* __restrict__ x,     // [Bn][Tn][IN_DIM]
    const float* __restrict__ Wih0,  // [H][IN_DIM]
    const float* __restrict__ Wih,   // [4][H][H]
    const float* __restrict__ Whh,   // [5][H][H]
    const float* __restrict__ bih,   // [5][H]
    const float* __restrict__ bhh,   // [5][H]
    const float* __restrict__ h0,    // [5][Bn][H]
    float* __restrict__ hf)          // [5][Bn][H]
{
    extern __shared__ __align__(16) unsigned char smraw[];
    const int tid = threadIdx.x;
    const int bid = blockIdx.x;

    if (bid < NGEMM) {
        unsigned long long* Wo  = (unsigned long long*)(smraw + SM_WO);
        float*              hb  = (float*)(smraw + SM_HB);
        unsigned long long* bsm = (unsigned long long*)(smraw + SM_BS);
        const int row  = tid & 63;
        const int half = tid >> 6;

        // ---------- Phase 1: xp0 for batch b0 = bid (bid < 64) ----------
        if (bid < Bn) {
            const int b0 = bid;
            // Stage Wih0 pairs: Wo[k][half][i] = (W[2m][k], W[2m+1][k])
            for (int idx = tid; idx < IN_DIM * 50; idx += 128) {
                int k = idx % IN_DIM, m = idx / IN_DIM;
                int hh = m / 25, i = m - hh * 25;
                Wo[k * 52 + hh * 26 + i] =
                    pack2(Wih0[(2 * m) * IN_DIM + k], Wih0[(2 * m + 1) * IN_DIM + k]);
            }
            for (int m = tid; m < 50; m += 128)
                bsm[m] = pack2(bih[2 * m] + bhh[2 * m], bih[2 * m + 1] + bhh[2 * m + 1]);
            __syncthreads();

            for (int c = 0; c < NCHUNK; c++) {
                const float* xr = x + ((size_t)b0 * Tn + (size_t)c * CCH + row) * IN_DIM;
                float xv[IN_DIM];
#pragma unroll
                for (int k = 0; k < IN_DIM; k++) xv[k] = xr[k];
                unsigned long long acc[25];
#pragma unroll
                for (int i = 0; i < 25; i++) acc[i] = bsm[half * 25 + i];
#pragma unroll
                for (int k = 0; k < IN_DIM; k++) {
                    unsigned long long xkk = pack2(xv[k], xv[k]);
                    const unsigned long long* Wk = Wo + k * 52 + half * 26;
#pragma unroll
                    for (int i = 0; i < 25; i++) acc[i] = fma2(xkk, Wk[i], acc[i]);
                }
                unsigned long long* dst = (unsigned long long*)
                    (g_xp + ((size_t)b0 * Tn + (size_t)c * CCH + row) * H + half * 50);
#pragma unroll
                for (int i = 0; i < 25; i++) dst[i] = acc[i];
                __syncthreads();
                if (tid == 0) {
                    __threadfence();
                    *(volatile int*)&g_flags[NREC + b0] = (c + 1) * CCH;   // xp flag, l=0
                }
                __syncthreads();
            }
            __syncthreads();
        }

        // ---------- Phase 2: layer-l input transform ----------
        const int l = 1 + bid / 31;          // 1..4
        const int r = bid % 31;
        const float* W = Wih + (size_t)(l - 1) * H * H;
        for (int idx = tid; idx < H * 50; idx += 128) {
            int k = idx % H, m = idx / H;
            int hh = m / 25, i = m - hh * 25;
            Wo[k * 52 + hh * 26 + i] = pack2(W[(2 * m) * H + k], W[(2 * m + 1) * H + k]);
        }
        for (int m = tid; m < 50; m += 128) {
            bsm[m] = pack2(bih[l * H + 2 * m] + bhh[l * H + 2 * m],
                           bih[l * H + 2 * m + 1] + bhh[l * H + 2 * m + 1]);
        }
        __syncthreads();

        const int nb = (r < 2) ? 3 : 2;
        for (int c = 0; c < NCHUNK; c++) {
            for (int ib = 0; ib < nb; ib++) {
                const int b = r + 31 * ib;
                const int need = (c + 1) * CCH;
                const int* rf = &g_flags[(l - 1) * Bn + b];
                int f;
                while ((f = acq_load(rf)) < need) __nanosleep(400);

                const float* src = g_h + (((size_t)(l - 1) * Bn + b) * Tn + (size_t)c * CCH) * H;
                for (int idx = tid; idx < CCH * H; idx += 128) {
                    int rr = idx / H, k = idx - rr * H;
                    hb[rr * 101 + k] = ldcg(src + idx);
                }
                __syncthreads();

                unsigned long long acc[25];
#pragma unroll
                for (int i = 0; i < 25; i++) acc[i] = bsm[half * 25 + i];
                const float* hrow = hb + row * 101;
#pragma unroll 2
                for (int k = 0; k < H; k++) {
                    float xk = hrow[k];
                    unsigned long long xkk = pack2(xk, xk);
                    const unsigned long long* Wk = Wo + k * 52 + half * 26;
#pragma unroll
                    for (int i = 0; i < 25; i++) acc[i] = fma2(xkk, Wk[i], acc[i]);
                }
                unsigned long long* dst = (unsigned long long*)
                    (g_xp + (((size_t)l * Bn + b) * Tn + (size_t)c * CCH + row) * H + half * 50);
#pragma unroll
                for (int i = 0; i < 25; i++) dst[i] = acc[i];
                __syncthreads();
                if (tid == 0) {
                    __threadfence();
                    *(volatile int*)&g_flags[NREC + l * Bn + b] = need;    // xp flag, layer l
                }
                __syncthreads();
            }
        }
        return;
    }

    // ======================= RECURRENT CTA =======================
    const int rb = bid - NGEMM;
    const int l = rb / Bn;
    const int b = rb % Bn;
    const int j = tid;

    float* hs0 = (float*)smraw;          // [104]
    float* hs1 = hs0 + 104;

    unsigned long long w[50];
    if (j < H) {
        const unsigned long long* wr = (const unsigned long long*)(Whh + ((size_t)l * H + j) * H);
#pragma unroll
        for (int i = 0; i < 50; i++) w[i] = wr[i];
        hs0[j] = h0[((size_t)l * Bn + b) * H + j];
    }
    __syncthreads();

    const float* xp = g_xp + ((size_t)l * Bn + b) * Tn * H;
    float* hout = g_h + ((size_t)l * Bn + b) * Tn * H;
    const int* srcflag = &g_flags[NREC + l * Bn + b];      // xp ready (all layers)
    volatile int* pubflag = (l < 4) ? (volatile int*)&g_flags[l * Bn + b] : nullptr;

    int seen = 0;
    while (seen < 1) seen = acq_load(srcflag);
    float xv = (j < H) ? ldcg(xp + j) : 0.f;

#pragma unroll 1
    for (int t = 0; t < Tn; t++) {
        float xnext = 0.f;
        if (t + 1 < Tn) {
            while (seen < t + 2) seen = acq_load(srcflag);   // jumps by CCH: rare
            if (j < H) xnext = ldcg(xp + (size_t)(t + 1) * H + j);
        }
        const int p = t & 1;
        if (j < H) {
            const ulonglong2* hp = (const ulonglong2*)(p ? hs1 : hs0);
            unsigned long long a0 = 0ull, a1 = 0ull, a2 = 0ull, a3 = 0ull;
            // 5 groups of 5 pairs: bounded LDS pipelining (<=5 hv live) to
            // stay under the 170-reg cap without spilling.
#pragma unroll
            for (int g = 0; g < 5; g++) {
#pragma unroll
                for (int q = 0; q < 5; q++) {
                    const int i = g * 5 + q;
                    ulonglong2 hv = hp[i];
                    if (i & 1) {
                        a2 = fma2(w[2 * i],     hv.x, a2);
                        a3 = fma2(w[2 * i + 1], hv.y, a3);
                    } else {
                        a0 = fma2(w[2 * i],     hv.x, a0);
                        a1 = fma2(w[2 * i + 1], hv.y, a1);
                    }
                }
                asm volatile("" ::: "memory");
            }
            unsigned long long s2 = add2(add2(a0, a2), add2(a1, a3));
            float slo, shi;
            unpack2(s2, slo, shi);
            float s = slo + shi + xv;
            float e  = __expf(2.0f * s);
            float th = 1.0f - __fdividef(2.0f, e + 1.0f);
            (p ? hs0 : hs1)[j] = th;
            hout[(size_t)t * H + j] = th;
        }
        __syncthreads();
        // Chunked publish: fence + flag only once per CCH steps.
        if (pubflag != nullptr && ((t + 1) & (CCH - 1)) == 0 && tid == 0) {
            __threadfence();
            *pubflag = t + 1;
        }
        xv = xnext;
    }

    if (j < H) hf[((size_t)l * Bn + b) * H + j] = hs0[j];   // Tn even -> final in hs0
}

// ---------------- output projection ----------------
__global__ void __launch_bounds__(128) proj_kernel(
    const float* __restrict__ X, const float* __restrict__ Wout,
    const float* __restrict__ bout, float* __restrict__ Y)
{
    __shared__ __align__(16) float Ws[H * 12];
    __shared__ __align__(16) float bs[12];
    const int tid = threadIdx.x;
    for (int i = tid; i < H * 12; i += 128) Ws[i] = 0.f;
    if (tid < 12) bs[tid] = (tid < OUT_D) ? bout[tid] : 0.f;
    __syncthreads();
    for (int idx = tid; idx < OUT_D * H; idx += 128) {
        int j = idx / H, k = idx - j * H;
        Ws[k * 12 + j] = Wout[idx];
    }
    __syncthreads();

    const int row = blockIdx.x * 128 + tid;
    if (row >= M_ROWS) return;

    unsigned long long acc[5];
    const unsigned long long* bp = (const unsigned long long*)bs;
#pragma unroll
    for (int i = 0; i < 5; i++) acc[i] = bp[i];
    const float4* xr = (const float4*)(X + (size_t)row * H);
#pragma unroll 1
    for (int k4 = 0; k4 < 25; k4++) {
        float4 xv = xr[k4];
        float xs[4] = {xv.x, xv.y, xv.z, xv.w};
#pragma unroll
        for (int u = 0; u < 4; u++) {
            int k = k4 * 4 + u;
            unsigned long long xkk = pack2(xs[u], xs[u]);
            const unsigned long long* wr = (const unsigned long long*)(Ws + k * 12);
#pragma unroll
            for (int i = 0; i < 5; i++) acc[i] = fma2(xkk, wr[i], acc[i]);
        }
    }
    unsigned long long* yr = (unsigned long long*)(Y + (size_t)row * OUT_D);
#pragma unroll
    for (int i = 0; i < 5; i++) yr[i] = acc[i];
}

// ---------------- launcher ----------------
extern "C" void kernel_launch(void* const* d_in, const int* in_sizes, int n_in,
                              void* d_out, int out_size)
{
    const float* x    = (const float*)d_in[0];
    const float* h0   = (const float*)d_in[1];
    const float* Wih0 = (const float*)d_in[2];
    const float* Wih  = (const float*)d_in[3];
    const float* Whh  = (const float*)d_in[4];
    const float* bih  = (const float*)d_in[5];
    const float* bhh  = (const float*)d_in[6];
    const float* Wout = (const float*)d_in[7];
    const float* bout = (const float*)d_in[8];

    float* y  = (float*)d_out;                        // [B,T,OUT]
    float* hf = y + (size_t)Bn * Tn * OUT_D;          // [L,B,H]

    float* hbuf;
    cudaGetSymbolAddress((void**)&hbuf, g_h);

    cudaFuncSetAttribute(fused_kernel, cudaFuncAttributeMaxDynamicSharedMemorySize, SM_SZ);

    zflags_kernel<<<1, 1024>>>();
    fused_kernel<<<GRID_F, 128, SM_SZ>>>(x, Wih0, Wih, Whh, bih, bhh, h0, hf);
    proj_kernel<<<(M_ROWS + 127) / 128, 128>>>(hbuf + (size_t)4 * Bn * Tn * H, Wout, bout, y);
}